// round 3
// baseline (speedup 1.0000x reference)
#include <cuda_runtime.h>
#include <cstdint>
#include <cstddef>

#define TST 192
#define BAT 256
#define HID 512
#define G4  2048
#define RWS (TST*BAT)

__device__ float g_X[(size_t)RWS*64];
__device__ float g_XZ[(size_t)RWS*G4];
__device__ float g_H1[(size_t)RWS*HID];
__device__ float g_H2[(size_t)RWS*HID];
__device__ float g_Hb[2][BAT*HID];
__device__ float g_Wk1p[64*G4];
__device__ float g_Wk2r[HID*G4];
__device__ unsigned g_cnt;
__device__ volatile unsigned g_flag;

__device__ __forceinline__ float rna(float x){
    unsigned r; asm("cvt.rna.tf32.f32 %0, %1;" : "=r"(r) : "f"(x));
    return __uint_as_float(r);
}
__device__ __forceinline__ void mma8(float* d, float a0,float a1,float a2,float a3,
                                     float b0,float b1){
    asm volatile("mma.sync.aligned.m16n8k8.row.col.f32.tf32.tf32.f32 "
        "{%0,%1,%2,%3}, {%4,%5,%6,%7}, {%8,%9}, {%0,%1,%2,%3};\n"
        : "+f"(d[0]),"+f"(d[1]),"+f"(d[2]),"+f"(d[3])
        : "r"(__float_as_uint(a0)),"r"(__float_as_uint(a1)),
          "r"(__float_as_uint(a2)),"r"(__float_as_uint(a3)),
          "r"(__float_as_uint(b0)),"r"(__float_as_uint(b1)));
}
__device__ __forceinline__ unsigned su32(const void* p){
    return (unsigned)__cvta_generic_to_shared(p);
}
__device__ __forceinline__ void cp16(unsigned dst, const void* src){
    asm volatile("cp.async.cg.shared.global [%0], [%1], 16;" :: "r"(dst), "l"(src));
}
__device__ __forceinline__ void cpc(){ asm volatile("cp.async.commit_group;"); }
template<int N> __device__ __forceinline__ void cpw(){
    asm volatile("cp.async.wait_group %0;" :: "n"(N));
}
__device__ __forceinline__ float sigf(float x){ return 1.f/(1.f+__expf(-x)); }
__device__ __forceinline__ float tanhf_(float x){
    float e=__expf(-2.f*fabsf(x)); return copysignf((1.f-e)/(1.f+e), x);
}

// ---------------- prep: embed/concat + weight rounding ----------------
__global__ void prep_k(const float* __restrict__ xc, const int* __restrict__ c0,
                       const int* __restrict__ c1, const float* __restrict__ e0,
                       const float* __restrict__ e1, const float* __restrict__ Wk1,
                       const float* __restrict__ Wk2){
    const size_t N1=(size_t)RWS*64, N2=N1+64*G4, NT=N2+(size_t)HID*G4;
    for(size_t i=(size_t)blockIdx.x*blockDim.x+threadIdx.x; i<NT;
        i+=(size_t)gridDim.x*blockDim.x){
        if(i<N1){
            int r=(int)(i>>6), cc=(int)(i&63), t=r>>8, b=r&255;
            float v=0.f;
            if(cc<8)       v=xc[(b*TST+t)*8+cc];
            else if(cc<40) v=e0[(size_t)c0[b*TST+t]*32+(cc-8)];
            else if(cc<56) v=e1[(size_t)c1[b*TST+t]*16+(cc-40)];
            g_X[i]=rna(v);
        } else if(i<N2){
            size_t j=i-N1; int k=(int)(j>>11);
            g_Wk1p[j]=(k<56)? rna(Wk1[(size_t)k*G4+(j&2047)]) : 0.f;
        } else {
            size_t j=i-N2; g_Wk2r[j]=rna(Wk2[j]);
        }
    }
}

__global__ void zero_k(){
    int i=blockIdx.x*blockDim.x+threadIdx.x;
    if(i<2*BAT*HID) ((float*)g_Hb)[i]=0.f;
}

// ---------------- GEMM: C[M,2048] = A[M,K]@W[K,2048] + bias ----------------
__global__ __launch_bounds__(128) void gemm64(const float* __restrict__ A,
        const float* __restrict__ W, const float* __restrict__ bias,
        float* __restrict__ C, int K){
    extern __shared__ float sm[];
    const int tid=threadIdx.x, l=tid&31, w=tid>>5, wm=w>>1, wn=w&1;
    const int g=l>>2, tg=l&3;
    const int row0=blockIdx.y*64, col0=blockIdx.x*64;
    float acc[2][4][4];
#pragma unroll
    for(int m=0;m<2;m++) for(int n=0;n<4;n++) for(int q=0;q<4;q++) acc[m][n][q]=0.f;
    const int NC=K>>6;

    auto issue=[&](int c){
        float* As_=sm+(c&1)*9216; float* Bs_=As_+4608;
#pragma unroll
        for(int q=0;q<8;q++){ int e=tid+128*q, r=e>>4, s=e&15;
            cp16(su32(As_+r*72+s*4), A+(size_t)(row0+r)*K + c*64 + s*4); }
#pragma unroll
        for(int q=0;q<8;q++){ int e=tid+128*q, r=e>>4, s=e&15;
            cp16(su32(Bs_+r*72+s*4), W+(size_t)(c*64+r)*G4 + col0 + s*4); }
    };
    issue(0); cpc();
    for(int c=0;c<NC;c++){
        if(c+1<NC){ issue(c+1); cpc(); cpw<1>(); } else cpw<0>();
        __syncthreads();
        const float* As_=sm+(c&1)*9216; const float* Bs_=As_+4608;
#pragma unroll
        for(int kb=0;kb<8;kb++){
            float a[2][4];
#pragma unroll
            for(int mt=0;mt<2;mt++){
                int r=wm*32+mt*16+g;
                a[mt][0]=As_[r*72+kb*8+tg];     a[mt][1]=As_[(r+8)*72+kb*8+tg];
                a[mt][2]=As_[r*72+kb*8+tg+4];   a[mt][3]=As_[(r+8)*72+kb*8+tg+4];
            }
#pragma unroll
            for(int nt=0;nt<4;nt++){
                int cc=wn*32+nt*8+g;
                float b0=Bs_[(kb*8+tg)*72+cc], b1=Bs_[(kb*8+tg+4)*72+cc];
                mma8(acc[0][nt],a[0][0],a[0][1],a[0][2],a[0][3],b0,b1);
                mma8(acc[1][nt],a[1][0],a[1][1],a[1][2],a[1][3],b0,b1);
            }
        }
        __syncthreads();
    }
#pragma unroll
    for(int nt=0;nt<4;nt++){
        int cc=col0+wn*32+nt*8+tg*2;
        float bx=bias[cc], by=bias[cc+1];
#pragma unroll
        for(int mt=0;mt<2;mt++){
            int r=row0+wm*32+mt*16+g;
            float2 v0={acc[mt][nt][0]+bx, acc[mt][nt][1]+by};
            float2 v1={acc[mt][nt][2]+bx, acc[mt][nt][3]+by};
            *(float2*)&C[(size_t)r*G4+cc]=v0;
            *(float2*)&C[(size_t)(r+8)*G4+cc]=v1;
        }
    }
}

// ---------------- persistent LSTM layer ----------------
// 128 CTAs = 4 batch-groups x 32 strips; CTA: 64 rows x 16 units x 4 gates.
__global__ __launch_bounds__(128) void lstm_k(const float* __restrict__ xz,
        float* __restrict__ hout, const float* __restrict__ Wr){
    extern __shared__ float sm[];
    float2* Wpk=(float2*)sm;            // 16384 float2 = 128 KB
    float* As=sm+32768;                 // 2 x 4608 floats
    const int tid=threadIdx.x, l=tid&31, w=tid>>5, wm=w>>1, wn=w&1;
    const int g=l>>2, tg=l&3;
    const int strip=blockIdx.x&31, bg=blockIdx.x>>5;

    // prepack Wr slice into B-fragment lane order:
    // Wpk[(kb*64 + ci)*4 + tg] = {Wr[kb*8+tg][gcol], Wr[kb*8+tg+4][gcol]},
    // ci = nt*16 + wn*8 + g,  gcol = nt*512 + strip*16 + wn*8 + g
    for(int e=tid;e<16384;e+=128){
        int tg_=e&3, ci=(e>>2)&63, kb=e>>8;
        int nt=ci>>4, wn_=(ci>>3)&1, gg=ci&7;
        int gcol=nt*HID + strip*16 + wn_*8 + gg;
        int k0=kb*8+tg_;
        float2 v; v.x=rna(Wr[(size_t)k0*G4+gcol]); v.y=rna(Wr[(size_t)(k0+4)*G4+gcol]);
        Wpk[e]=v;
    }
    __syncthreads();

    float cst[2][4];
#pragma unroll
    for(int m=0;m<2;m++) for(int q=0;q<4;q++) cst[m][q]=0.f;
    unsigned sense=0;

    for(int t=0;t<TST;t++){
        const float* hb=g_Hb[t&1];
        float* hn=g_Hb[(t&1)^1];
        {   float* dst=As;
#pragma unroll
            for(int q=0;q<8;q++){ int e=tid+128*q, r=e>>4, s=e&15;
                cp16(su32(dst+r*72+s*4), hb+(size_t)(bg*64+r)*HID + s*4); }
            cpc();
        }
        float acc[2][4][4];
        const float* xr=xz+(size_t)t*BAT*G4;
#pragma unroll
        for(int mt=0;mt<2;mt++)
#pragma unroll
            for(int nt=0;nt<4;nt++){
                int b=bg*64+wm*32+mt*16+g;
                int cc=nt*HID+strip*16+wn*8+tg*2;
                float2 v0=*(const float2*)&xr[(size_t)b*G4+cc];
                float2 v1=*(const float2*)&xr[(size_t)(b+8)*G4+cc];
                acc[mt][nt][0]=v0.x; acc[mt][nt][1]=v0.y;
                acc[mt][nt][2]=v1.x; acc[mt][nt][3]=v1.y;
            }
        for(int c=0;c<8;c++){
            if(c<7){
                float* dst=As+((c+1)&1)*4608;
#pragma unroll
                for(int q=0;q<8;q++){ int e=tid+128*q, r=e>>4, s=e&15;
                    cp16(su32(dst+r*72+s*4), hb+(size_t)(bg*64+r)*HID+(c+1)*64+s*4); }
                cpc(); cpw<1>();
            } else cpw<0>();
            __syncthreads();
            const float* A_=As+(c&1)*4608;
#pragma unroll
            for(int kb=0;kb<8;kb++){
                float a[2][4];
#pragma unroll
                for(int mt=0;mt<2;mt++){
                    int r=wm*32+mt*16+g;
                    a[mt][0]=A_[r*72+kb*8+tg];   a[mt][1]=A_[(r+8)*72+kb*8+tg];
                    a[mt][2]=A_[r*72+kb*8+tg+4]; a[mt][3]=A_[(r+8)*72+kb*8+tg+4];
                }
                int kbg=c*8+kb;
#pragma unroll
                for(int nt=0;nt<4;nt++){
                    float2 bv=Wpk[(kbg*64 + nt*16+wn*8+g)*4 + tg];
                    mma8(acc[0][nt],a[0][0],a[0][1],a[0][2],a[0][3],bv.x,bv.y);
                    mma8(acc[1][nt],a[1][0],a[1][1],a[1][2],a[1][3],bv.x,bv.y);
                }
            }
            __syncthreads();
        }
        // gates (thread-local: acc[mt][gate][q] all same (row,unit))
#pragma unroll
        for(int mt=0;mt<2;mt++)
#pragma unroll
            for(int q=0;q<4;q++){
                float ig=sigf(acc[mt][0][q]);
                float fg=sigf(acc[mt][1][q]);
                float gv=tanhf_(acc[mt][2][q]);
                float og=sigf(acc[mt][3][q]);
                float cc_=fg*cst[mt][q]+ig*gv;
                cst[mt][q]=cc_;
                float h=rna(og*tanhf_(cc_));
                int b=bg*64+wm*32+mt*16+(q>>1)*8+g;
                int U=strip*16+wn*8+tg*2+(q&1);
                hout[(size_t)(t*BAT+b)*HID+U]=h;
                hn[b*HID+U]=h;
            }
        // grid barrier (all 128 CTAs co-resident; even flips -> replay-safe)
        __threadfence(); __syncthreads();
        if(tid==0){
            unsigned tgt=sense^1u;
            if(atomicAdd(&g_cnt,1u)==127u){ g_cnt=0u; __threadfence(); g_flag=tgt; }
            else { while(g_flag!=tgt){} __threadfence(); }
        }
        __syncthreads();
        sense^=1u;
    }
}

// ---------------- heads ----------------
__global__ __launch_bounds__(256) void head_k(const float* __restrict__ h,
        const float* __restrict__ Wmu, const float* __restrict__ bmu,
        const float* __restrict__ Wsig, const float* __restrict__ bsig,
        float* __restrict__ out){
    int w=threadIdx.x>>5, l=threadIdx.x&31;
    int r=blockIdx.x*8+w;
    const float* hr=h+(size_t)r*HID;
    float smu=0.f, ssg=0.f;
    for(int k=l;k<HID;k+=32){ float hv=hr[k]; smu+=hv*Wmu[k]; ssg+=hv*Wsig[k]; }
#pragma unroll
    for(int o=16;o;o>>=1){
        smu+=__shfl_xor_sync(0xFFFFFFFFu,smu,o);
        ssg+=__shfl_xor_sync(0xFFFFFFFFu,ssg,o);
    }
    if(l==0){
        int t=r>>8, b=r&255;
        out[b*TST+t]=smu+bmu[0];
        float x=ssg+bsig[0];
        out[RWS + b*TST+t]=(x>20.f)? x : log1pf(__expf(x));
    }
}

extern "C" void kernel_launch(void* const* d_in, const int* in_sizes, int n_in,
                              void* d_out, int out_size){
    const float* xc  =(const float*)d_in[0];
    const int*   c0  =(const int*  )d_in[1];
    const int*   c1  =(const int*  )d_in[2];
    const float* e0  =(const float*)d_in[3];
    const float* e1  =(const float*)d_in[4];
    const float* Wk1 =(const float*)d_in[5];
    const float* Wr1 =(const float*)d_in[6];
    const float* b1  =(const float*)d_in[7];
    const float* Wk2 =(const float*)d_in[8];
    const float* Wr2 =(const float*)d_in[9];
    const float* b2  =(const float*)d_in[10];
    const float* Wmu =(const float*)d_in[11];
    const float* bmu =(const float*)d_in[12];
    const float* Wsig=(const float*)d_in[13];
    const float* bsig=(const float*)d_in[14];
    float* out=(float*)d_out;

    cudaFuncSetAttribute(lstm_k,  cudaFuncAttributeMaxDynamicSharedMemorySize, 167936);
    cudaFuncSetAttribute(gemm64, cudaFuncAttributeMaxDynamicSharedMemorySize, 73728);

    void *pX,*pXZ,*pH1,*pH2,*pW1,*pW2;
    cudaGetSymbolAddress(&pX,  g_X);
    cudaGetSymbolAddress(&pXZ, g_XZ);
    cudaGetSymbolAddress(&pH1, g_H1);
    cudaGetSymbolAddress(&pH2, g_H2);
    cudaGetSymbolAddress(&pW1, g_Wk1p);
    cudaGetSymbolAddress(&pW2, g_Wk2r);

    prep_k<<<4096,256>>>(xc,c0,c1,e0,e1,Wk1,Wk2);
    zero_k<<<1024,256>>>();
    gemm64<<<dim3(32,RWS/64),128,73728>>>((const float*)pX,(const float*)pW1,b1,(float*)pXZ,64);
    lstm_k<<<128,128,167936>>>((const float*)pXZ,(float*)pH1,Wr1);
    zero_k<<<1024,256>>>();
    gemm64<<<dim3(32,RWS/64),128,73728>>>((const float*)pH1,(const float*)pW2,b2,(float*)pXZ,512);
    lstm_k<<<128,128,167936>>>((const float*)pXZ,(float*)pH2,Wr2);
    head_k<<<RWS/8,256>>>((const float*)pH2,Wmu,bmu,Wsig,bsig,out);
}

// round 4
// speedup vs baseline: 1.1348x; 1.1348x over previous
#include <cuda_runtime.h>
#include <cstdint>
#include <cstddef>

#define TST 192
#define BAT 256
#define HID 512
#define G4  2048
#define RWS (TST*BAT)

__device__ float g_X[(size_t)RWS*64];
__device__ float g_XZ[(size_t)RWS*G4];
__device__ float g_H1[(size_t)RWS*HID];
__device__ float g_H2[(size_t)RWS*HID];
__device__ float g_Hb[2][64*BAT*8];      // fragment-packed h ping-pong [kb][b][8]
__device__ float g_Wk1p[64*G4];
__device__ float g_Wk2r[HID*G4];
__device__ unsigned g_cnt[128];          // per-batch-group barrier (bg*32), line-padded
__device__ volatile unsigned g_flag[128];

__device__ __forceinline__ float rna(float x){
    unsigned r; asm("cvt.rna.tf32.f32 %0, %1;" : "=r"(r) : "f"(x));
    return __uint_as_float(r);
}
__device__ __forceinline__ void mma8(float* d, float a0,float a1,float a2,float a3,
                                     float b0,float b1){
    asm volatile("mma.sync.aligned.m16n8k8.row.col.f32.tf32.tf32.f32 "
        "{%0,%1,%2,%3}, {%4,%5,%6,%7}, {%8,%9}, {%0,%1,%2,%3};\n"
        : "+f"(d[0]),"+f"(d[1]),"+f"(d[2]),"+f"(d[3])
        : "r"(__float_as_uint(a0)),"r"(__float_as_uint(a1)),
          "r"(__float_as_uint(a2)),"r"(__float_as_uint(a3)),
          "r"(__float_as_uint(b0)),"r"(__float_as_uint(b1)));
}
__device__ __forceinline__ unsigned su32(const void* p){
    return (unsigned)__cvta_generic_to_shared(p);
}
__device__ __forceinline__ void cp16(unsigned dst, const void* src){
    asm volatile("cp.async.cg.shared.global [%0], [%1], 16;" :: "r"(dst), "l"(src));
}
__device__ __forceinline__ void cpc(){ asm volatile("cp.async.commit_group;"); }
template<int N> __device__ __forceinline__ void cpw(){
    asm volatile("cp.async.wait_group %0;" :: "n"(N));
}
__device__ __forceinline__ float sigf(float x){ return 1.f/(1.f+__expf(-x)); }
__device__ __forceinline__ float tanhf_(float x){
    float e=__expf(-2.f*fabsf(x)); return copysignf((1.f-e)/(1.f+e), x);
}

// ---------------- prep: embed/concat + weight rounding ----------------
__global__ void prep_k(const float* __restrict__ xc, const int* __restrict__ c0,
                       const int* __restrict__ c1, const float* __restrict__ e0,
                       const float* __restrict__ e1, const float* __restrict__ Wk1,
                       const float* __restrict__ Wk2){
    const size_t N1=(size_t)RWS*64, N2=N1+64*G4, NT=N2+(size_t)HID*G4;
    for(size_t i=(size_t)blockIdx.x*blockDim.x+threadIdx.x; i<NT;
        i+=(size_t)gridDim.x*blockDim.x){
        if(i<N1){
            int r=(int)(i>>6), cc=(int)(i&63), t=r>>8, b=r&255;
            float v=0.f;
            if(cc<8)       v=xc[(b*TST+t)*8+cc];
            else if(cc<40) v=e0[(size_t)c0[b*TST+t]*32+(cc-8)];
            else if(cc<56) v=e1[(size_t)c1[b*TST+t]*16+(cc-40)];
            g_X[i]=rna(v);
        } else if(i<N2){
            size_t j=i-N1; int k=(int)(j>>11);
            g_Wk1p[j]=(k<56)? rna(Wk1[(size_t)k*G4+(j&2047)]) : 0.f;
        } else {
            size_t j=i-N2; g_Wk2r[j]=rna(Wk2[j]);
        }
    }
}

__global__ void zero_k(){
    int i=blockIdx.x*blockDim.x+threadIdx.x;
    if(i<2*64*BAT*8) ((float*)g_Hb)[i]=0.f;
}

// ---------------- GEMM: C[M,2048] = A[M,K]@W[K,2048] + bias ----------------
__global__ __launch_bounds__(128) void gemm64(const float* __restrict__ A,
        const float* __restrict__ W, const float* __restrict__ bias,
        float* __restrict__ C, int K){
    extern __shared__ float sm[];
    const int tid=threadIdx.x, l=tid&31, w=tid>>5, wm=w>>1, wn=w&1;
    const int g=l>>2, tg=l&3;
    const int row0=blockIdx.y*64, col0=blockIdx.x*64;
    float acc[2][4][4];
#pragma unroll
    for(int m=0;m<2;m++) for(int n=0;n<4;n++) for(int q=0;q<4;q++) acc[m][n][q]=0.f;
    const int NC=K>>6;

    auto issue=[&](int c){
        float* As_=sm+(c&1)*9216; float* Bs_=As_+4608;
#pragma unroll
        for(int q=0;q<8;q++){ int e=tid+128*q, r=e>>4, s=e&15;
            cp16(su32(As_+r*72+s*4), A+(size_t)(row0+r)*K + c*64 + s*4); }
#pragma unroll
        for(int q=0;q<8;q++){ int e=tid+128*q, r=e>>4, s=e&15;
            cp16(su32(Bs_+r*72+s*4), W+(size_t)(c*64+r)*G4 + col0 + s*4); }
    };
    issue(0); cpc();
    for(int c=0;c<NC;c++){
        if(c+1<NC){ issue(c+1); cpc(); cpw<1>(); } else cpw<0>();
        __syncthreads();
        const float* As_=sm+(c&1)*9216; const float* Bs_=As_+4608;
#pragma unroll
        for(int kb=0;kb<8;kb++){
            float a[2][4];
#pragma unroll
            for(int mt=0;mt<2;mt++){
                int r=wm*32+mt*16+g;
                a[mt][0]=As_[r*72+kb*8+tg];     a[mt][1]=As_[(r+8)*72+kb*8+tg];
                a[mt][2]=As_[r*72+kb*8+tg+4];   a[mt][3]=As_[(r+8)*72+kb*8+tg+4];
            }
#pragma unroll
            for(int nt=0;nt<4;nt++){
                int cc=wn*32+nt*8+g;
                float b0=Bs_[(kb*8+tg)*72+cc], b1=Bs_[(kb*8+tg+4)*72+cc];
                mma8(acc[0][nt],a[0][0],a[0][1],a[0][2],a[0][3],b0,b1);
                mma8(acc[1][nt],a[1][0],a[1][1],a[1][2],a[1][3],b0,b1);
            }
        }
        __syncthreads();
    }
#pragma unroll
    for(int nt=0;nt<4;nt++){
        int cc=col0+wn*32+nt*8+tg*2;
        float bx=bias[cc], by=bias[cc+1];
#pragma unroll
        for(int mt=0;mt<2;mt++){
            int r=row0+wm*32+mt*16+g;
            float2 v0={acc[mt][nt][0]+bx, acc[mt][nt][1]+by};
            float2 v1={acc[mt][nt][2]+bx, acc[mt][nt][3]+by};
            *(float2*)&C[(size_t)r*G4+cc]=v0;
            *(float2*)&C[(size_t)(r+8)*G4+cc]=v1;
        }
    }
}

// ---------------- persistent LSTM layer ----------------
// 128 CTAs = 4 batch-groups x 32 strips; CTA: 64 rows x 16 units x 4 gates.
// 256 threads = 2 warp-groups K-split (wg0: k<256, wg1: k>=256) + SMEM reduction.
__global__ __launch_bounds__(256) void lstm_k(const float* __restrict__ xz,
        float* __restrict__ hout, const float* __restrict__ Wr){
    extern __shared__ float sm[];
    float2* Wpk=(float2*)sm;            // 16384 float2 = 128 KB
    float* red=sm+49152;                // 4224 floats (128 x stride 33)
    const int tid=threadIdx.x, l=tid&31, w=tid>>5;
    const int wg=w>>2, wl=w&3;
    const int wm=wl>>1, wn=wl&1;
    const int g=l>>2, tg=l&3;
    const int wtid=tid&127;
    const int strip=blockIdx.x&31, bg=blockIdx.x>>5;
    float* As0=sm+32768+wg*8192;        // 2 x 4096-float stages per warp-group

    // prepack Wr slice into B-fragment lane order
    for(int e=tid;e<16384;e+=256){
        int tg_=e&3, ci=(e>>2)&63, kb=e>>8;
        int nt=ci>>4, wn_=(ci>>3)&1, gg=ci&7;
        int gcol=nt*HID + strip*16 + wn_*8 + gg;
        int k0=kb*8+tg_;
        float2 v; v.x=rna(Wr[(size_t)k0*G4+gcol]); v.y=rna(Wr[(size_t)(k0+4)*G4+gcol]);
        Wpk[e]=v;
    }
    __syncthreads();

    float cst[2][4];
#pragma unroll
    for(int m=0;m<2;m++) for(int q=0;q<4;q++) cst[m][q]=0.f;
    unsigned sense=0;

    for(int t=0;t<TST;t++){
        const float* hb=g_Hb[t&1];
        float* hn=g_Hb[(t&1)^1];

        auto issueA=[&](int c){
            float* dst=As0+(c&1)*4096;
            const int kb0=wg*32+c*8;
#pragma unroll
            for(int q=0;q<8;q++){
                int e=wtid+128*q;
                int kbl=e>>7, rem=e&127, r=rem>>1, hf=rem&1;
                cp16(su32(dst+(kbl*64+r)*8+hf*4),
                     hb + ((size_t)(kb0+kbl)*BAT + bg*64 + r)*8 + hf*4);
            }
        };
        issueA(0); cpc();

        float acc[2][4][4];
        if(wg==0){
            const float* xr=xz+(size_t)t*BAT*G4;
#pragma unroll
            for(int mt=0;mt<2;mt++)
#pragma unroll
                for(int nt=0;nt<4;nt++){
                    int b=bg*64+wm*32+mt*16+g;
                    int cc=nt*HID+strip*16+wn*8+tg*2;
                    float2 v0=*(const float2*)&xr[(size_t)b*G4+cc];
                    float2 v1=*(const float2*)&xr[(size_t)(b+8)*G4+cc];
                    acc[mt][nt][0]=v0.x; acc[mt][nt][1]=v0.y;
                    acc[mt][nt][2]=v1.x; acc[mt][nt][3]=v1.y;
                }
        } else {
#pragma unroll
            for(int m=0;m<2;m++) for(int n=0;n<4;n++) for(int q=0;q<4;q++)
                acc[m][n][q]=0.f;
        }

        for(int c=0;c<4;c++){
            if(c<3){ issueA(c+1); cpc(); cpw<1>(); } else cpw<0>();
            __syncthreads();
            const float* A_=As0+(c&1)*4096;
#pragma unroll
            for(int kbl=0;kbl<8;kbl++){
                const int kbg=wg*32+c*8+kbl;
                float2 v0[2], v1[2];
#pragma unroll
                for(int mt=0;mt<2;mt++){
                    int r=wm*32+mt*16+g;
                    v0[mt]=*(const float2*)&A_[(kbl*64+r)*8+tg*2];
                    v1[mt]=*(const float2*)&A_[(kbl*64+r+8)*8+tg*2];
                }
#pragma unroll
                for(int nt=0;nt<4;nt++){
                    float2 bv=Wpk[(kbg*64 + nt*16+wn*8+g)*4 + tg];
                    mma8(acc[0][nt], v0[0].x,v1[0].x,v0[0].y,v1[0].y, bv.x,bv.y);
                    mma8(acc[1][nt], v0[1].x,v1[1].x,v0[1].y,v1[1].y, bv.x,bv.y);
                }
            }
            __syncthreads();
        }

        // K-split reduction: wg1 -> SMEM, wg0 adds
        if(wg==1){
#pragma unroll
            for(int mt=0;mt<2;mt++)
#pragma unroll
                for(int nt=0;nt<4;nt++)
#pragma unroll
                    for(int q=0;q<4;q++)
                        red[wtid*33 + mt*16+nt*4+q]=acc[mt][nt][q];
        }
        __syncthreads();
        if(wg==0){
#pragma unroll
            for(int mt=0;mt<2;mt++)
#pragma unroll
                for(int q=0;q<4;q++){
                    float zi=acc[mt][0][q]+red[wtid*33+mt*16+q];
                    float zf=acc[mt][1][q]+red[wtid*33+mt*16+4+q];
                    float zg=acc[mt][2][q]+red[wtid*33+mt*16+8+q];
                    float zo=acc[mt][3][q]+red[wtid*33+mt*16+12+q];
                    float ig=sigf(zi), fg=sigf(zf), gv=tanhf_(zg), og=sigf(zo);
                    float cc_=fg*cst[mt][q]+ig*gv;
                    cst[mt][q]=cc_;
                    float h=rna(og*tanhf_(cc_));
                    int b=bg*64+wm*32+mt*16+(q>>1)*8+g;
                    int U=strip*16+wn*8+tg*2+(q&1);
                    hout[(size_t)(t*BAT+b)*HID+U]=h;
                    int kb=U>>3, kp=U&7, j=(kp&3)*2+(kp>>2);
                    hn[((size_t)kb*BAT+b)*8+j]=h;
                }
        }

        // per-batch-group grid barrier (32 CTAs; even flips -> replay-safe)
        __threadfence(); __syncthreads();
        if(tid==0){
            unsigned tgt=sense^1u;
            if(atomicAdd(&g_cnt[bg*32],1u)==31u){
                g_cnt[bg*32]=0u; __threadfence(); g_flag[bg*32]=tgt;
            } else { while(g_flag[bg*32]!=tgt){} __threadfence(); }
        }
        __syncthreads();
        sense^=1u;
    }
}

// ---------------- heads ----------------
__global__ __launch_bounds__(256) void head_k(const float* __restrict__ h,
        const float* __restrict__ Wmu, const float* __restrict__ bmu,
        const float* __restrict__ Wsig, const float* __restrict__ bsig,
        float* __restrict__ out){
    int w=threadIdx.x>>5, l=threadIdx.x&31;
    int r=blockIdx.x*8+w;
    const float* hr=h+(size_t)r*HID;
    float smu=0.f, ssg=0.f;
    for(int k=l;k<HID;k+=32){ float hv=hr[k]; smu+=hv*Wmu[k]; ssg+=hv*Wsig[k]; }
#pragma unroll
    for(int o=16;o;o>>=1){
        smu+=__shfl_xor_sync(0xFFFFFFFFu,smu,o);
        ssg+=__shfl_xor_sync(0xFFFFFFFFu,ssg,o);
    }
    if(l==0){
        int t=r>>8, b=r&255;
        out[b*TST+t]=smu+bmu[0];
        float x=ssg+bsig[0];
        out[RWS + b*TST+t]=(x>20.f)? x : log1pf(__expf(x));
    }
}

extern "C" void kernel_launch(void* const* d_in, const int* in_sizes, int n_in,
                              void* d_out, int out_size){
    const float* xc  =(const float*)d_in[0];
    const int*   c0  =(const int*  )d_in[1];
    const int*   c1  =(const int*  )d_in[2];
    const float* e0  =(const float*)d_in[3];
    const float* e1  =(const float*)d_in[4];
    const float* Wk1 =(const float*)d_in[5];
    const float* Wr1 =(const float*)d_in[6];
    const float* b1  =(const float*)d_in[7];
    const float* Wk2 =(const float*)d_in[8];
    const float* Wr2 =(const float*)d_in[9];
    const float* b2  =(const float*)d_in[10];
    const float* Wmu =(const float*)d_in[11];
    const float* bmu =(const float*)d_in[12];
    const float* Wsig=(const float*)d_in[13];
    const float* bsig=(const float*)d_in[14];
    float* out=(float*)d_out;

    cudaFuncSetAttribute(lstm_k, cudaFuncAttributeMaxDynamicSharedMemorySize, 213504);
    cudaFuncSetAttribute(gemm64, cudaFuncAttributeMaxDynamicSharedMemorySize, 73728);

    void *pX,*pXZ,*pH1,*pH2,*pW1,*pW2;
    cudaGetSymbolAddress(&pX,  g_X);
    cudaGetSymbolAddress(&pXZ, g_XZ);
    cudaGetSymbolAddress(&pH1, g_H1);
    cudaGetSymbolAddress(&pH2, g_H2);
    cudaGetSymbolAddress(&pW1, g_Wk1p);
    cudaGetSymbolAddress(&pW2, g_Wk2r);

    prep_k<<<4096,256>>>(xc,c0,c1,e0,e1,Wk1,Wk2);
    zero_k<<<1024,256>>>();
    gemm64<<<dim3(32,RWS/64),128,73728>>>((const float*)pX,(const float*)pW1,b1,(float*)pXZ,64);
    lstm_k<<<128,256,213504>>>((const float*)pXZ,(float*)pH1,Wr1);
    zero_k<<<1024,256>>>();
    gemm64<<<dim3(32,RWS/64),128,73728>>>((const float*)pH1,(const float*)pW2,b2,(float*)pXZ,512);
    lstm_k<<<128,256,213504>>>((const float*)pXZ,(float*)pH2,Wr2);
    head_k<<<RWS/8,256>>>((const float*)pH2,Wmu,bmu,Wsig,bsig,out);
}